// round 2
// baseline (speedup 1.0000x reference)
#include <cuda_runtime.h>
#include <cstdint>

// ---------------------------------------------------------------------------
// CrossAttentionDecoder: B=1024 (8x128), n_tok=16, num_latents=128, DIM=512,
// 8 heads x dh=64. Mask: batch b attends to latents j <= b%128.
//
// Pipeline (tf32 mma.sync everywhere):
//   1) proj_kernel mode 0 : g_Q = (x @ Wq^T) * 0.125      (M=16384)
//   2) kv_kernel          : g_K/g_V = l[b] @ Wk^T / Wv^T  (only rows < L=b%128+1)
//   3) attn_kernel        : per-batch attention -> g_O
//   4) proj_kernel mode 1 : out = g_O @ Wo^T + bo         (M=16384)
// ---------------------------------------------------------------------------

#define DIM 512
#define NLAT 128
#define NTOK 16
#define NHEAD 8
#define DH 64
#define NB 1024

// scratch (device globals: allocation-free)
__device__ float g_Q[(size_t)NB * NTOK * DIM];        // 33.5 MB
__device__ float g_K[(size_t)NB * NLAT * DIM];        // 268 MB
__device__ float g_V[(size_t)NB * NLAT * DIM];        // 268 MB
__device__ float g_O[(size_t)NB * NTOK * DIM];        // 33.5 MB

// smem sizes (floats)
#define PROJ_SMEM_F (128 * 68 + 64 * 68)
#define KV_SMEM_F   (128 * 68 + 2 * 64 * 68)
#define ATTN_SMEM_F (16 * 516 + 32 * 516 + 8 * 16 * 132)

__device__ __forceinline__ float cvt_tf32(float x) {
    uint32_t u;
    asm("cvt.rna.tf32.f32 %0, %1;" : "=r"(u) : "f"(x));
    return __uint_as_float(u);
}
__device__ __forceinline__ float4 cvt_tf32_4(float4 v) {
    v.x = cvt_tf32(v.x); v.y = cvt_tf32(v.y);
    v.z = cvt_tf32(v.z); v.w = cvt_tf32(v.w);
    return v;
}
__device__ __forceinline__ void mma_tf32(float* c, uint32_t a0, uint32_t a1,
                                         uint32_t a2, uint32_t a3,
                                         uint32_t b0, uint32_t b1) {
    asm volatile(
        "mma.sync.aligned.m16n8k8.row.col.f32.tf32.tf32.f32 "
        "{%0,%1,%2,%3}, {%4,%5,%6,%7}, {%8,%9}, {%0,%1,%2,%3};\n"
        : "+f"(c[0]), "+f"(c[1]), "+f"(c[2]), "+f"(c[3])
        : "r"(a0), "r"(a1), "r"(a2), "r"(a3), "r"(b0), "r"(b1));
}

// ---------------------------------------------------------------------------
// Generic C[M,512] = scale * A[M,512] @ W^T (+ bias). Block: 128m x 64n.
// mode 0: A = Ain (x), C = g_Q.   mode 1: A = g_O, C = Cout (d_out).
// ---------------------------------------------------------------------------
__global__ __launch_bounds__(256) void proj_kernel(
    const float* __restrict__ Ain, const float* __restrict__ W,
    float* __restrict__ Cout, const float* __restrict__ bias,
    float scale, int mode)
{
    extern __shared__ float sm[];
    float* As = sm;              // [128][68]
    float* Ws = sm + 128 * 68;   // [64][68]

    const float* A = (mode == 0) ? Ain : g_O;
    float* C = (mode == 0) ? g_Q : Cout;

    const int n0 = blockIdx.x * 64;
    const int m0 = blockIdx.y * 128;
    const int tid = threadIdx.x;
    const int warp = tid >> 5, lane = tid & 31;
    const int g = lane >> 2, t = lane & 3;
    const int mw = warp * 16;

    float c[8][4];
#pragma unroll
    for (int f = 0; f < 8; f++)
#pragma unroll
        for (int e = 0; e < 4; e++) c[f][e] = 0.f;

    for (int kc = 0; kc < 8; kc++) {
        const int k0g = kc * 64;
#pragma unroll
        for (int it = 0; it < 8; it++) {            // A: 128 x 16 float4
            int idx = tid + it * 256;
            int r = idx >> 4, c4 = idx & 15;
            float4 v = *reinterpret_cast<const float4*>(
                A + (size_t)(m0 + r) * DIM + k0g + c4 * 4);
            *reinterpret_cast<float4*>(As + r * 68 + c4 * 4) = cvt_tf32_4(v);
        }
#pragma unroll
        for (int it = 0; it < 4; it++) {            // W: 64 x 16 float4
            int idx = tid + it * 256;
            int r = idx >> 4, c4 = idx & 15;
            float4 v = *reinterpret_cast<const float4*>(
                W + (size_t)(n0 + r) * DIM + k0g + c4 * 4);
            *reinterpret_cast<float4*>(Ws + r * 68 + c4 * 4) = cvt_tf32_4(v);
        }
        __syncthreads();
#pragma unroll
        for (int ks = 0; ks < 8; ks++) {
            const int k0 = ks * 8;
            uint32_t a0 = __float_as_uint(As[(mw + g) * 68 + k0 + t]);
            uint32_t a1 = __float_as_uint(As[(mw + g + 8) * 68 + k0 + t]);
            uint32_t a2 = __float_as_uint(As[(mw + g) * 68 + k0 + t + 4]);
            uint32_t a3 = __float_as_uint(As[(mw + g + 8) * 68 + k0 + t + 4]);
#pragma unroll
            for (int f = 0; f < 8; f++) {
                uint32_t b0 = __float_as_uint(Ws[(f * 8 + g) * 68 + k0 + t]);
                uint32_t b1 = __float_as_uint(Ws[(f * 8 + g) * 68 + k0 + t + 4]);
                mma_tf32(c[f], a0, a1, a2, a3, b0, b1);
            }
        }
        __syncthreads();
    }
#pragma unroll
    for (int f = 0; f < 8; f++) {
        const int col = n0 + f * 8 + 2 * t;
        float b0 = bias ? bias[col] : 0.f;
        float b1 = bias ? bias[col + 1] : 0.f;
        const int row0 = m0 + mw + g;
        float2 v0 = make_float2(c[f][0] * scale + b0, c[f][1] * scale + b1);
        float2 v1 = make_float2(c[f][2] * scale + b0, c[f][3] * scale + b1);
        *reinterpret_cast<float2*>(C + (size_t)row0 * DIM + col) = v0;
        *reinterpret_cast<float2*>(C + (size_t)(row0 + 8) * DIM + col) = v1;
    }
}

// ---------------------------------------------------------------------------
// K/V projection, mask-aware: block = (n-chunk, batch). Computes only the
// warp tiles covering rows < L = b%128 + 1, K and V share the A tile.
// ---------------------------------------------------------------------------
__global__ __launch_bounds__(256) void kv_kernel(
    const float* __restrict__ l,
    const float* __restrict__ Wk, const float* __restrict__ Wv)
{
    extern __shared__ float sm[];
    float* As  = sm;                       // [128][68]
    float* Wks = sm + 128 * 68;            // [64][68]
    float* Wvs = Wks + 64 * 68;            // [64][68]

    const int n0 = blockIdx.x * 64;
    const int b  = blockIdx.y;
    const int m  = b & (NLAT - 1);
    const int L  = m + 1;
    const int ntiles = (L + 15) >> 4;
    const int rows = ntiles << 4;

    const int tid = threadIdx.x;
    const int warp = tid >> 5, lane = tid & 31;
    const int g = lane >> 2, t = lane & 3;
    const int mw = warp * 16;
    const bool active = (warp < ntiles);

    const float* Ab = l + (size_t)b * NLAT * DIM;

    float ck[8][4], cv[8][4];
#pragma unroll
    for (int f = 0; f < 8; f++)
#pragma unroll
        for (int e = 0; e < 4; e++) { ck[f][e] = 0.f; cv[f][e] = 0.f; }

    for (int kc = 0; kc < 8; kc++) {
        const int k0g = kc * 64;
#pragma unroll
        for (int it = 0; it < 8; it++) {
            int idx = tid + it * 256;
            int r = idx >> 4, c4 = idx & 15;
            if (r < rows) {
                float4 v = *reinterpret_cast<const float4*>(
                    Ab + (size_t)r * DIM + k0g + c4 * 4);
                *reinterpret_cast<float4*>(As + r * 68 + c4 * 4) = cvt_tf32_4(v);
            }
        }
#pragma unroll
        for (int it = 0; it < 4; it++) {
            int idx = tid + it * 256;
            int r = idx >> 4, c4 = idx & 15;
            float4 vk = *reinterpret_cast<const float4*>(
                Wk + (size_t)(n0 + r) * DIM + k0g + c4 * 4);
            float4 vv = *reinterpret_cast<const float4*>(
                Wv + (size_t)(n0 + r) * DIM + k0g + c4 * 4);
            *reinterpret_cast<float4*>(Wks + r * 68 + c4 * 4) = cvt_tf32_4(vk);
            *reinterpret_cast<float4*>(Wvs + r * 68 + c4 * 4) = cvt_tf32_4(vv);
        }
        __syncthreads();
        if (active) {
#pragma unroll
            for (int ks = 0; ks < 8; ks++) {
                const int k0 = ks * 8;
                uint32_t a0 = __float_as_uint(As[(mw + g) * 68 + k0 + t]);
                uint32_t a1 = __float_as_uint(As[(mw + g + 8) * 68 + k0 + t]);
                uint32_t a2 = __float_as_uint(As[(mw + g) * 68 + k0 + t + 4]);
                uint32_t a3 = __float_as_uint(As[(mw + g + 8) * 68 + k0 + t + 4]);
#pragma unroll
                for (int f = 0; f < 8; f++) {
                    uint32_t bk0 = __float_as_uint(Wks[(f * 8 + g) * 68 + k0 + t]);
                    uint32_t bk1 = __float_as_uint(Wks[(f * 8 + g) * 68 + k0 + t + 4]);
                    mma_tf32(ck[f], a0, a1, a2, a3, bk0, bk1);
                    uint32_t bv0 = __float_as_uint(Wvs[(f * 8 + g) * 68 + k0 + t]);
                    uint32_t bv1 = __float_as_uint(Wvs[(f * 8 + g) * 68 + k0 + t + 4]);
                    mma_tf32(cv[f], a0, a1, a2, a3, bv0, bv1);
                }
            }
        }
        __syncthreads();
    }
    if (active) {
        const int j0 = mw + g;
#pragma unroll
        for (int f = 0; f < 8; f++) {
            const int col = n0 + f * 8 + 2 * t;
            if (j0 < L) {
                size_t o = ((size_t)b * NLAT + j0) * DIM + col;
                *reinterpret_cast<float2*>(g_K + o) = make_float2(ck[f][0], ck[f][1]);
                *reinterpret_cast<float2*>(g_V + o) = make_float2(cv[f][0], cv[f][1]);
            }
            if (j0 + 8 < L) {
                size_t o = ((size_t)b * NLAT + j0 + 8) * DIM + col;
                *reinterpret_cast<float2*>(g_K + o) = make_float2(ck[f][2], ck[f][3]);
                *reinterpret_cast<float2*>(g_V + o) = make_float2(cv[f][2], cv[f][3]);
            }
        }
    }
}

// ---------------------------------------------------------------------------
// Attention: one block per batch element, warp = head.
// scores (16x128) in registers -> masked softmax -> attn in smem -> PV.
// ---------------------------------------------------------------------------
__global__ __launch_bounds__(256) void attn_kernel()
{
    extern __shared__ float sm[];
    float* q_s  = sm;                    // [16][516]
    float* kv_s = sm + 16 * 516;         // [32][516]
    float* s_s  = kv_s + 32 * 516;       // [8][16][132]

    const int b = blockIdx.x;
    const int m = b & (NLAT - 1);
    const int njt = (m >> 5) + 1;        // needed 32-latent tiles

    const int tid = threadIdx.x;
    const int h = tid >> 5, lane = tid & 31;
    const int g = lane >> 2, t = lane & 3;

    // stage Q (tf32-rounded; scale 1/8 already folded in)
#pragma unroll
    for (int it = 0; it < 8; it++) {
        int idx = tid + it * 256;        // 0..2047 float4s
        int r = idx >> 7, c4 = idx & 127;
        float4 v = *reinterpret_cast<const float4*>(
            g_Q + ((size_t)b * NTOK + r) * DIM + c4 * 4);
        *reinterpret_cast<float4*>(q_s + r * 516 + c4 * 4) = cvt_tf32_4(v);
    }
    __syncthreads();

    // preload q fragments for this head (K-dim = 64 -> 8 k-steps)
    uint32_t aq[8][4];
#pragma unroll
    for (int ks = 0; ks < 8; ks++) {
        const int col = h * DH + ks * 8;
        aq[ks][0] = __float_as_uint(q_s[g * 516 + col + t]);
        aq[ks][1] = __float_as_uint(q_s[(g + 8) * 516 + col + t]);
        aq[ks][2] = __float_as_uint(q_s[g * 516 + col + t + 4]);
        aq[ks][3] = __float_as_uint(q_s[(g + 8) * 516 + col + t + 4]);
    }

    float cs[16][4];
#pragma unroll
    for (int f = 0; f < 16; f++)
#pragma unroll
        for (int e = 0; e < 4; e++) cs[f][e] = 0.f;

    // ---- phase A: scores = q @ k^T (per head) ----
    for (int jt = 0; jt < 4; jt++) {
        if (jt < njt) {
#pragma unroll
            for (int it = 0; it < 16; it++) {      // 32 x 128 float4
                int idx = tid + it * 256;
                int r = idx >> 7, c4 = idx & 127;
                int j = jt * 32 + r;
                float4 v = make_float4(0.f, 0.f, 0.f, 0.f);
                if (j <= m)
                    v = cvt_tf32_4(*reinterpret_cast<const float4*>(
                        g_K + ((size_t)b * NLAT + j) * DIM + c4 * 4));
                *reinterpret_cast<float4*>(kv_s + r * 516 + c4 * 4) = v;
            }
            __syncthreads();
#pragma unroll
            for (int ks = 0; ks < 8; ks++) {
                const int col = h * DH + ks * 8;
#pragma unroll
                for (int jn = 0; jn < 4; jn++) {
                    uint32_t b0 = __float_as_uint(kv_s[(jn * 8 + g) * 516 + col + t]);
                    uint32_t b1 = __float_as_uint(kv_s[(jn * 8 + g) * 516 + col + t + 4]);
                    mma_tf32(cs[jt * 4 + jn], aq[ks][0], aq[ks][1], aq[ks][2], aq[ks][3], b0, b1);
                }
            }
            __syncthreads();
        }
    }

    // ---- masked softmax over j (two rows per thread: g, g+8) ----
    float mx0 = -1e30f, mx1 = -1e30f;
#pragma unroll
    for (int f = 0; f < 16; f++) {
        const int jb = (f >> 2) * 32 + (f & 3) * 8 + 2 * t;
#pragma unroll
        for (int e = 0; e < 2; e++) {
            if (jb + e > m) { cs[f][e] = -1e30f; cs[f][2 + e] = -1e30f; }
            mx0 = fmaxf(mx0, cs[f][e]);
            mx1 = fmaxf(mx1, cs[f][2 + e]);
        }
    }
    mx0 = fmaxf(mx0, __shfl_xor_sync(0xffffffffu, mx0, 1));
    mx0 = fmaxf(mx0, __shfl_xor_sync(0xffffffffu, mx0, 2));
    mx1 = fmaxf(mx1, __shfl_xor_sync(0xffffffffu, mx1, 1));
    mx1 = fmaxf(mx1, __shfl_xor_sync(0xffffffffu, mx1, 2));
    float s0 = 0.f, s1 = 0.f;
#pragma unroll
    for (int f = 0; f < 16; f++)
#pragma unroll
        for (int e = 0; e < 2; e++) {
            cs[f][e] = __expf(cs[f][e] - mx0);     s0 += cs[f][e];
            cs[f][2 + e] = __expf(cs[f][2 + e] - mx1); s1 += cs[f][2 + e];
        }
    s0 += __shfl_xor_sync(0xffffffffu, s0, 1);
    s0 += __shfl_xor_sync(0xffffffffu, s0, 2);
    s1 += __shfl_xor_sync(0xffffffffu, s1, 1);
    s1 += __shfl_xor_sync(0xffffffffu, s1, 2);
    const float i0 = 1.f / s0, i1 = 1.f / s1;
#pragma unroll
    for (int f = 0; f < 16; f++) {
        const int jb = (f >> 2) * 32 + (f & 3) * 8 + 2 * t;
#pragma unroll
        for (int e = 0; e < 2; e++) {
            s_s[(h * 16 + g) * 132 + jb + e]     = cvt_tf32(cs[f][e] * i0);
            s_s[(h * 16 + g + 8) * 132 + jb + e] = cvt_tf32(cs[f][2 + e] * i1);
        }
    }

    // ---- phase B: out = attn @ v (per head) ----
    float co[8][4];
#pragma unroll
    for (int f = 0; f < 8; f++)
#pragma unroll
        for (int e = 0; e < 4; e++) co[f][e] = 0.f;

    for (int jt = 0; jt < njt; jt++) {
#pragma unroll
        for (int it = 0; it < 16; it++) {          // stage V tile (zero-fill masked)
            int idx = tid + it * 256;
            int r = idx >> 7, c4 = idx & 127;
            int j = jt * 32 + r;
            float4 v = make_float4(0.f, 0.f, 0.f, 0.f);
            if (j <= m)
                v = cvt_tf32_4(*reinterpret_cast<const float4*>(
                    g_V + ((size_t)b * NLAT + j) * DIM + c4 * 4));
            *reinterpret_cast<float4*>(kv_s + r * 516 + c4 * 4) = v;
        }
        __syncthreads();
#pragma unroll
        for (int ks2 = 0; ks2 < 4; ks2++) {
            const int jb = ks2 * 8;
            uint32_t a0 = __float_as_uint(s_s[(h * 16 + g) * 132 + jt * 32 + jb + t]);
            uint32_t a1 = __float_as_uint(s_s[(h * 16 + g + 8) * 132 + jt * 32 + jb + t]);
            uint32_t a2 = __float_as_uint(s_s[(h * 16 + g) * 132 + jt * 32 + jb + t + 4]);
            uint32_t a3 = __float_as_uint(s_s[(h * 16 + g + 8) * 132 + jt * 32 + jb + t + 4]);
#pragma unroll
            for (int dn = 0; dn < 8; dn++) {
                const int col = h * DH + dn * 8 + g;
                uint32_t b0 = __float_as_uint(kv_s[(jb + t) * 516 + col]);
                uint32_t b1 = __float_as_uint(kv_s[(jb + t + 4) * 516 + col]);
                mma_tf32(co[dn], a0, a1, a2, a3, b0, b1);
            }
        }
        __syncthreads();
    }

    // store attention output
#pragma unroll
    for (int dn = 0; dn < 8; dn++) {
        const int col = h * DH + dn * 8 + 2 * t;
        size_t o0 = ((size_t)b * NTOK + g) * DIM + col;
        size_t o1 = ((size_t)b * NTOK + g + 8) * DIM + col;
        *reinterpret_cast<float2*>(g_O + o0) = make_float2(co[dn][0], co[dn][1]);
        *reinterpret_cast<float2*>(g_O + o1) = make_float2(co[dn][2], co[dn][3]);
    }
}

// ---------------------------------------------------------------------------
extern "C" void kernel_launch(void* const* d_in, const int* in_sizes, int n_in,
                              void* d_out, int out_size)
{
    const float* x  = (const float*)d_in[0];
    const float* l  = (const float*)d_in[1];
    const float* Wq = (const float*)d_in[2];
    const float* Wk = (const float*)d_in[3];
    const float* Wv = (const float*)d_in[4];
    const float* Wo = (const float*)d_in[5];
    const float* bo = (const float*)d_in[6];
    float* out = (float*)d_out;

    const int smem_proj = PROJ_SMEM_F * 4;
    const int smem_kv   = KV_SMEM_F * 4;
    const int smem_attn = ATTN_SMEM_F * 4;

    cudaFuncSetAttribute(proj_kernel, cudaFuncAttributeMaxDynamicSharedMemorySize, smem_proj);
    cudaFuncSetAttribute(kv_kernel,   cudaFuncAttributeMaxDynamicSharedMemorySize, smem_kv);
    cudaFuncSetAttribute(attn_kernel, cudaFuncAttributeMaxDynamicSharedMemorySize, smem_attn);

    // 1) Q = (x @ Wq^T) / 8
    proj_kernel<<<dim3(8, 128), 256, smem_proj>>>(x, Wq, nullptr, nullptr, 0.125f, 0);
    // 2) K, V (masked rows skipped)
    kv_kernel<<<dim3(8, 1024), 256, smem_kv>>>(l, Wk, Wv);
    // 3) attention per batch element
    attn_kernel<<<1024, 256, smem_attn>>>();
    // 4) out = O @ Wo^T + bo
    proj_kernel<<<dim3(8, 128), 256, smem_proj>>>(nullptr, Wo, out, bo, 1.0f, 1);
}

// round 3
// speedup vs baseline: 1.3601x; 1.3601x over previous
#include <cuda_runtime.h>
#include <cstdint>

// ---------------------------------------------------------------------------
// CrossAttentionDecoder restructured: K/V never materialized.
//   scores_h = (q_h @ Wk_h) @ l^T ;  out_h = (attn_h @ l) @ Wv_h^T
//
//   K1 proj  : g_Q  = (x @ Wq^T) * 0.125            (16384x512, K=512)
//   K2 qk    : g_QK[b,h,i,:] = g_Q[b*16+i, h*64:+64] @ Wk[h*64:+64, :]  (K=64)
//   K3 attn  : per batch: scores = qk @ l^T (masked), softmax,
//              g_AL = attn @ l                        (streams l, L2-hot)
//   K4 ov    : g_OV[:, h*64:+64] = g_AL_h @ Wv_h^T   (K=512, N=64)
//   K5 proj  : out = g_OV @ Wo^T + bo                (K=512)
// ---------------------------------------------------------------------------

#define DIM 512
#define NLAT 128
#define NTOK 16
#define NHEAD 8
#define DH 64
#define NB 1024

// scratch (device globals: allocation-free)
__device__ float g_Q [(size_t)NB * NTOK * DIM];          // 33.5 MB
__device__ float g_QK[(size_t)NB * NHEAD * NTOK * DIM];  // 268 MB  [b][h][i][e]
__device__ float g_AL[(size_t)NB * NHEAD * NTOK * DIM];  // 268 MB  [b][h][i][e]
__device__ float g_OV[(size_t)NB * NTOK * DIM];          // 33.5 MB

// smem sizes (floats)
#define PROJ_SMEM_F (128 * 68 + 64 * 68)
#define QK_SMEM_F   (128 * 68 + 64 * 72)
#define OV_SMEM_F   (128 * 68 + 64 * 68)
#define ATTN_SMEM_F (128 * 68 + 128 * 68 + 128 * 132)

__device__ __forceinline__ float cvt_tf32(float x) {
    uint32_t u;
    asm("cvt.rna.tf32.f32 %0, %1;" : "=r"(u) : "f"(x));
    return __uint_as_float(u);
}
__device__ __forceinline__ float4 cvt_tf32_4(float4 v) {
    v.x = cvt_tf32(v.x); v.y = cvt_tf32(v.y);
    v.z = cvt_tf32(v.z); v.w = cvt_tf32(v.w);
    return v;
}
__device__ __forceinline__ void mma_tf32(float* c, uint32_t a0, uint32_t a1,
                                         uint32_t a2, uint32_t a3,
                                         uint32_t b0, uint32_t b1) {
    asm volatile(
        "mma.sync.aligned.m16n8k8.row.col.f32.tf32.tf32.f32 "
        "{%0,%1,%2,%3}, {%4,%5,%6,%7}, {%8,%9}, {%0,%1,%2,%3};\n"
        : "+f"(c[0]), "+f"(c[1]), "+f"(c[2]), "+f"(c[3])
        : "r"(a0), "r"(a1), "r"(a2), "r"(a3), "r"(b0), "r"(b1));
}

// ---------------------------------------------------------------------------
// K1/K5: C[M,512] = scale * A[M,512] @ W^T (+ bias). Block: 128m x 64n.
// mode 0: A = Ain (x), C = g_Q.   mode 1: A = g_OV, C = Cout (d_out).
// ---------------------------------------------------------------------------
__global__ __launch_bounds__(256) void proj_kernel(
    const float* __restrict__ Ain, const float* __restrict__ W,
    float* __restrict__ Cout, const float* __restrict__ bias,
    float scale, int mode)
{
    extern __shared__ float sm[];
    float* As = sm;              // [128][68]
    float* Ws = sm + 128 * 68;   // [64][68]  Ws[n][k]

    const float* A = (mode == 0) ? Ain : g_OV;
    float* C = (mode == 0) ? g_Q : Cout;

    const int n0 = blockIdx.x * 64;
    const int m0 = blockIdx.y * 128;
    const int tid = threadIdx.x;
    const int warp = tid >> 5, lane = tid & 31;
    const int g = lane >> 2, t = lane & 3;
    const int mw = warp * 16;

    float c[8][4];
#pragma unroll
    for (int f = 0; f < 8; f++)
#pragma unroll
        for (int e = 0; e < 4; e++) c[f][e] = 0.f;

    for (int kc = 0; kc < 8; kc++) {
        const int k0g = kc * 64;
#pragma unroll
        for (int it = 0; it < 8; it++) {            // A: 128 x 16 float4
            int idx = tid + it * 256;
            int r = idx >> 4, c4 = idx & 15;
            float4 v = *reinterpret_cast<const float4*>(
                A + (size_t)(m0 + r) * DIM + k0g + c4 * 4);
            *reinterpret_cast<float4*>(As + r * 68 + c4 * 4) = cvt_tf32_4(v);
        }
#pragma unroll
        for (int it = 0; it < 4; it++) {            // W: 64 x 16 float4
            int idx = tid + it * 256;
            int r = idx >> 4, c4 = idx & 15;
            float4 v = *reinterpret_cast<const float4*>(
                W + (size_t)(n0 + r) * DIM + k0g + c4 * 4);
            *reinterpret_cast<float4*>(Ws + r * 68 + c4 * 4) = cvt_tf32_4(v);
        }
        __syncthreads();
#pragma unroll
        for (int ks = 0; ks < 8; ks++) {
            const int k0 = ks * 8;
            uint32_t a0 = __float_as_uint(As[(mw + g) * 68 + k0 + t]);
            uint32_t a1 = __float_as_uint(As[(mw + g + 8) * 68 + k0 + t]);
            uint32_t a2 = __float_as_uint(As[(mw + g) * 68 + k0 + t + 4]);
            uint32_t a3 = __float_as_uint(As[(mw + g + 8) * 68 + k0 + t + 4]);
#pragma unroll
            for (int f = 0; f < 8; f++) {
                uint32_t b0 = __float_as_uint(Ws[(f * 8 + g) * 68 + k0 + t]);
                uint32_t b1 = __float_as_uint(Ws[(f * 8 + g) * 68 + k0 + t + 4]);
                mma_tf32(c[f], a0, a1, a2, a3, b0, b1);
            }
        }
        __syncthreads();
    }
#pragma unroll
    for (int f = 0; f < 8; f++) {
        const int col = n0 + f * 8 + 2 * t;
        float b0 = bias ? bias[col] : 0.f;
        float b1 = bias ? bias[col + 1] : 0.f;
        const int row0 = m0 + mw + g;
        float2 v0 = make_float2(c[f][0] * scale + b0, c[f][1] * scale + b1);
        float2 v1 = make_float2(c[f][2] * scale + b0, c[f][3] * scale + b1);
        *reinterpret_cast<float2*>(C + (size_t)row0 * DIM + col) = v0;
        *reinterpret_cast<float2*>(C + (size_t)(row0 + 8) * DIM + col) = v1;
    }
}

// ---------------------------------------------------------------------------
// K2: g_QK[b][h][i][e] = sum_d g_Q[b*16+i][h*64+d] * Wk[h*64+d][e]   (K=64)
// grid (8 ntiles, 128 mtiles, 8 heads)
// ---------------------------------------------------------------------------
__global__ __launch_bounds__(256) void qk_kernel(const float* __restrict__ Wk)
{
    extern __shared__ float sm[];
    float* As = sm;              // [128][68]  As[r][k]
    float* Bs = sm + 128 * 68;   // [64][72]   Bs[k][n]

    const int n0 = blockIdx.x * 64;
    const int m0 = blockIdx.y * 128;
    const int h  = blockIdx.z;
    const int tid = threadIdx.x;
    const int warp = tid >> 5, lane = tid & 31;
    const int g = lane >> 2, t = lane & 3;
    const int mw = warp * 16;

    // stage A: rows m0..+128, cols h*64..+64
#pragma unroll
    for (int it = 0; it < 8; it++) {
        int idx = tid + it * 256;
        int r = idx >> 4, c4 = idx & 15;
        float4 v = *reinterpret_cast<const float4*>(
            g_Q + (size_t)(m0 + r) * DIM + h * DH + c4 * 4);
        *reinterpret_cast<float4*>(As + r * 68 + c4 * 4) = cvt_tf32_4(v);
    }
    // stage B: Bs[k][n] = Wk[h*64+k][n0+n]
#pragma unroll
    for (int it = 0; it < 4; it++) {
        int idx = tid + it * 256;
        int k = idx >> 4, c4 = idx & 15;
        float4 v = *reinterpret_cast<const float4*>(
            Wk + (size_t)(h * DH + k) * DIM + n0 + c4 * 4);
        *reinterpret_cast<float4*>(Bs + k * 72 + c4 * 4) = cvt_tf32_4(v);
    }
    __syncthreads();

    float c[8][4];
#pragma unroll
    for (int f = 0; f < 8; f++)
#pragma unroll
        for (int e = 0; e < 4; e++) c[f][e] = 0.f;

#pragma unroll
    for (int ks = 0; ks < 8; ks++) {
        const int k0 = ks * 8;
        uint32_t a0 = __float_as_uint(As[(mw + g) * 68 + k0 + t]);
        uint32_t a1 = __float_as_uint(As[(mw + g + 8) * 68 + k0 + t]);
        uint32_t a2 = __float_as_uint(As[(mw + g) * 68 + k0 + t + 4]);
        uint32_t a3 = __float_as_uint(As[(mw + g + 8) * 68 + k0 + t + 4]);
#pragma unroll
        for (int f = 0; f < 8; f++) {
            uint32_t b0 = __float_as_uint(Bs[(k0 + t) * 72 + f * 8 + g]);
            uint32_t b1 = __float_as_uint(Bs[(k0 + t + 4) * 72 + f * 8 + g]);
            mma_tf32(c[f], a0, a1, a2, a3, b0, b1);
        }
    }

    // write: global A-row r0 = m0+mw+g -> b = r0>>4 (g<8 so b const per warp), i = g
    const int bb = (m0 + mw) >> 4;   // batch index
#pragma unroll
    for (int f = 0; f < 8; f++) {
        const int col = n0 + f * 8 + 2 * t;
        size_t o0 = (((size_t)bb * NHEAD + h) * NTOK + g) * DIM + col;
        size_t o1 = (((size_t)bb * NHEAD + h) * NTOK + g + 8) * DIM + col;
        *reinterpret_cast<float2*>(g_QK + o0) = make_float2(c[f][0], c[f][1]);
        *reinterpret_cast<float2*>(g_QK + o1) = make_float2(c[f][2], c[f][3]);
    }
}

// ---------------------------------------------------------------------------
// K3: per-batch attention. warp = head.
//   phase A: scores = qk @ l^T (masked), streaming e-chunks of 64
//   softmax (masked)
//   phase B: g_AL = attn @ l, streaming e-chunks (l re-read, L2-hot)
// ---------------------------------------------------------------------------
__global__ __launch_bounds__(256) void attn_kernel(const float* __restrict__ l)
{
    extern __shared__ float sm[];
    float* l_s  = sm;                    // [128][68]
    float* qk_s = sm + 128 * 68;         // [128][68]  (h*16+i rows)
    float* s_s  = qk_s + 128 * 68;       // [128][132] attn (h*16+i rows)

    const int b = blockIdx.x;
    const int m = b & (NLAT - 1);
    const int njt = (m >> 5) + 1;        // 32-row j tiles needed
    const int rows = njt << 5;

    const int tid = threadIdx.x;
    const int h = tid >> 5, lane = tid & 31;
    const int g = lane >> 2, t = lane & 3;

    const float* lb  = l + (size_t)b * NLAT * DIM;
    const float* qkb = g_QK + (size_t)b * NHEAD * NTOK * DIM;

    float cs[16][4];
#pragma unroll
    for (int f = 0; f < 16; f++)
#pragma unroll
        for (int e = 0; e < 4; e++) cs[f][e] = 0.f;

    // ---- phase A: scores ----
    for (int ec = 0; ec < 8; ec++) {
        const int e0 = ec * 64;
#pragma unroll
        for (int it = 0; it < 8; it++) {           // qk: 128 rows x 16 f4
            int idx = tid + it * 256;
            int r = idx >> 4, c4 = idx & 15;
            float4 v = *reinterpret_cast<const float4*>(
                qkb + (size_t)r * DIM + e0 + c4 * 4);
            *reinterpret_cast<float4*>(qk_s + r * 68 + c4 * 4) = cvt_tf32_4(v);
        }
#pragma unroll
        for (int it = 0; it < 8; it++) {           // l: rows [0,rows)
            int idx = tid + it * 256;
            int r = idx >> 4, c4 = idx & 15;
            if (r < rows) {
                float4 v = make_float4(0.f, 0.f, 0.f, 0.f);
                if (r <= m)
                    v = cvt_tf32_4(*reinterpret_cast<const float4*>(
                        lb + (size_t)r * DIM + e0 + c4 * 4));
                *reinterpret_cast<float4*>(l_s + r * 68 + c4 * 4) = v;
            }
        }
        __syncthreads();
#pragma unroll
        for (int kk = 0; kk < 8; kk++) {
            const int k0 = kk * 8;
            uint32_t a0 = __float_as_uint(qk_s[(h * 16 + g) * 68 + k0 + t]);
            uint32_t a1 = __float_as_uint(qk_s[(h * 16 + g + 8) * 68 + k0 + t]);
            uint32_t a2 = __float_as_uint(qk_s[(h * 16 + g) * 68 + k0 + t + 4]);
            uint32_t a3 = __float_as_uint(qk_s[(h * 16 + g + 8) * 68 + k0 + t + 4]);
#pragma unroll
            for (int jt = 0; jt < 4; jt++) {
                if (jt < njt) {
#pragma unroll
                    for (int jn = 0; jn < 4; jn++) {
                        const int jr = jt * 32 + jn * 8;
                        uint32_t b0 = __float_as_uint(l_s[(jr + g) * 68 + k0 + t]);
                        uint32_t b1 = __float_as_uint(l_s[(jr + g) * 68 + k0 + t + 4]);
                        mma_tf32(cs[jt * 4 + jn], a0, a1, a2, a3, b0, b1);
                    }
                }
            }
        }
        __syncthreads();
    }

    // ---- masked softmax (rows g and g+8 per thread) ----
    float mx0 = -1e30f, mx1 = -1e30f;
#pragma unroll
    for (int f = 0; f < 16; f++) {
        const int jb = f * 8 + 2 * t;
#pragma unroll
        for (int e = 0; e < 2; e++) {
            if (jb + e > m) { cs[f][e] = -1e30f; cs[f][2 + e] = -1e30f; }
            mx0 = fmaxf(mx0, cs[f][e]);
            mx1 = fmaxf(mx1, cs[f][2 + e]);
        }
    }
    mx0 = fmaxf(mx0, __shfl_xor_sync(0xffffffffu, mx0, 1));
    mx0 = fmaxf(mx0, __shfl_xor_sync(0xffffffffu, mx0, 2));
    mx1 = fmaxf(mx1, __shfl_xor_sync(0xffffffffu, mx1, 1));
    mx1 = fmaxf(mx1, __shfl_xor_sync(0xffffffffu, mx1, 2));
    float s0 = 0.f, s1 = 0.f;
#pragma unroll
    for (int f = 0; f < 16; f++)
#pragma unroll
        for (int e = 0; e < 2; e++) {
            cs[f][e] = __expf(cs[f][e] - mx0);         s0 += cs[f][e];
            cs[f][2 + e] = __expf(cs[f][2 + e] - mx1); s1 += cs[f][2 + e];
        }
    s0 += __shfl_xor_sync(0xffffffffu, s0, 1);
    s0 += __shfl_xor_sync(0xffffffffu, s0, 2);
    s1 += __shfl_xor_sync(0xffffffffu, s1, 1);
    s1 += __shfl_xor_sync(0xffffffffu, s1, 2);
    const float i0 = 1.f / s0, i1 = 1.f / s1;
#pragma unroll
    for (int f = 0; f < 16; f++) {
        const int jb = f * 8 + 2 * t;
#pragma unroll
        for (int e = 0; e < 2; e++) {
            s_s[(h * 16 + g) * 132 + jb + e]     = cvt_tf32(cs[f][e] * i0);
            s_s[(h * 16 + g + 8) * 132 + jb + e] = cvt_tf32(cs[f][2 + e] * i1);
        }
    }
    // s_s rows are private to the writing warp; no cross-warp sync needed.

    // ---- phase B: AL = attn @ l ----
    for (int ec = 0; ec < 8; ec++) {
        const int e0 = ec * 64;
#pragma unroll
        for (int it = 0; it < 8; it++) {           // restage l (L2-hot)
            int idx = tid + it * 256;
            int r = idx >> 4, c4 = idx & 15;
            if (r < rows) {
                float4 v = make_float4(0.f, 0.f, 0.f, 0.f);
                if (r <= m)
                    v = cvt_tf32_4(*reinterpret_cast<const float4*>(
                        lb + (size_t)r * DIM + e0 + c4 * 4));
                *reinterpret_cast<float4*>(l_s + r * 68 + c4 * 4) = v;
            }
        }
        __syncthreads();

        float co[8][4];
#pragma unroll
        for (int en = 0; en < 8; en++)
#pragma unroll
            for (int e = 0; e < 4; e++) co[en][e] = 0.f;

        for (int jc = 0; jc < njt * 4; jc++) {
            const int j0 = jc * 8;
            uint32_t a0 = __float_as_uint(s_s[(h * 16 + g) * 132 + j0 + t]);
            uint32_t a1 = __float_as_uint(s_s[(h * 16 + g + 8) * 132 + j0 + t]);
            uint32_t a2 = __float_as_uint(s_s[(h * 16 + g) * 132 + j0 + t + 4]);
            uint32_t a3 = __float_as_uint(s_s[(h * 16 + g + 8) * 132 + j0 + t + 4]);
#pragma unroll
            for (int en = 0; en < 8; en++) {
                uint32_t b0 = __float_as_uint(l_s[(j0 + t) * 68 + en * 8 + g]);
                uint32_t b1 = __float_as_uint(l_s[(j0 + t + 4) * 68 + en * 8 + g]);
                mma_tf32(co[en], a0, a1, a2, a3, b0, b1);
            }
        }
#pragma unroll
        for (int en = 0; en < 8; en++) {
            const int col = e0 + en * 8 + 2 * t;
            size_t o0 = ((size_t)b * (NHEAD * NTOK) + h * 16 + g) * DIM + col;
            size_t o1 = ((size_t)b * (NHEAD * NTOK) + h * 16 + g + 8) * DIM + col;
            *reinterpret_cast<float2*>(g_AL + o0) = make_float2(co[en][0], co[en][1]);
            *reinterpret_cast<float2*>(g_AL + o1) = make_float2(co[en][2], co[en][3]);
        }
        __syncthreads();
    }
}

// ---------------------------------------------------------------------------
// K4: g_OV[b*16+i][h*64+d] = sum_e g_AL[b][h][i][e] * Wv[h*64+d][e]
// grid (128 btiles of 8 batches, 8 heads), K=512, N=64
// ---------------------------------------------------------------------------
__global__ __launch_bounds__(256) void ov_kernel(const float* __restrict__ Wv)
{
    extern __shared__ float sm[];
    float* As = sm;              // [128][68]
    float* Bs = sm + 128 * 68;   // [64][68]  Bs[d][k]

    const int bt = blockIdx.x;   // 8 batches per block
    const int h  = blockIdx.y;
    const int tid = threadIdx.x;
    const int warp = tid >> 5, lane = tid & 31;
    const int g = lane >> 2, t = lane & 3;
    const int mw = warp * 16;

    float c[8][4];
#pragma unroll
    for (int f = 0; f < 8; f++)
#pragma unroll
        for (int e = 0; e < 4; e++) c[f][e] = 0.f;

    for (int kc = 0; kc < 8; kc++) {
        const int k0g = kc * 64;
#pragma unroll
        for (int it = 0; it < 8; it++) {           // A: 128 AL-rows x 16 f4
            int idx = tid + it * 256;
            int r = idx >> 4, c4 = idx & 15;
            size_t gr = (((size_t)(bt * 8 + (r >> 4)) * NHEAD + h) * NTOK + (r & 15));
            float4 v = *reinterpret_cast<const float4*>(
                g_AL + gr * DIM + k0g + c4 * 4);
            *reinterpret_cast<float4*>(As + r * 68 + c4 * 4) = cvt_tf32_4(v);
        }
#pragma unroll
        for (int it = 0; it < 4; it++) {           // B: Wv_h 64 x 16 f4
            int idx = tid + it * 256;
            int d = idx >> 4, c4 = idx & 15;
            float4 v = *reinterpret_cast<const float4*>(
                Wv + (size_t)(h * DH + d) * DIM + k0g + c4 * 4);
            *reinterpret_cast<float4*>(Bs + d * 68 + c4 * 4) = cvt_tf32_4(v);
        }
        __syncthreads();
#pragma unroll
        for (int ks = 0; ks < 8; ks++) {
            const int k0 = ks * 8;
            uint32_t a0 = __float_as_uint(As[(mw + g) * 68 + k0 + t]);
            uint32_t a1 = __float_as_uint(As[(mw + g + 8) * 68 + k0 + t]);
            uint32_t a2 = __float_as_uint(As[(mw + g) * 68 + k0 + t + 4]);
            uint32_t a3 = __float_as_uint(As[(mw + g + 8) * 68 + k0 + t + 4]);
#pragma unroll
            for (int f = 0; f < 8; f++) {
                uint32_t b0 = __float_as_uint(Bs[(f * 8 + g) * 68 + k0 + t]);
                uint32_t b1 = __float_as_uint(Bs[(f * 8 + g) * 68 + k0 + t + 4]);
                mma_tf32(c[f], a0, a1, a2, a3, b0, b1);
            }
        }
        __syncthreads();
    }

    // write g_OV: batch = bt*8 + warp (rloc>>4 = warp), i = g / g+8
    const int bb = bt * 8 + warp;
#pragma unroll
    for (int f = 0; f < 8; f++) {
        const int col = h * DH + f * 8 + 2 * t;
        size_t o0 = ((size_t)bb * NTOK + g) * DIM + col;
        size_t o1 = ((size_t)bb * NTOK + g + 8) * DIM + col;
        *reinterpret_cast<float2*>(g_OV + o0) = make_float2(c[f][0], c[f][1]);
        *reinterpret_cast<float2*>(g_OV + o1) = make_float2(c[f][2], c[f][3]);
    }
}

// ---------------------------------------------------------------------------
extern "C" void kernel_launch(void* const* d_in, const int* in_sizes, int n_in,
                              void* d_out, int out_size)
{
    const float* x  = (const float*)d_in[0];
    const float* l  = (const float*)d_in[1];
    const float* Wq = (const float*)d_in[2];
    const float* Wk = (const float*)d_in[3];
    const float* Wv = (const float*)d_in[4];
    const float* Wo = (const float*)d_in[5];
    const float* bo = (const float*)d_in[6];
    float* out = (float*)d_out;

    const int smem_proj = PROJ_SMEM_F * 4;
    const int smem_qk   = QK_SMEM_F * 4;
    const int smem_attn = ATTN_SMEM_F * 4;
    const int smem_ov   = OV_SMEM_F * 4;

    cudaFuncSetAttribute(proj_kernel, cudaFuncAttributeMaxDynamicSharedMemorySize, smem_proj);
    cudaFuncSetAttribute(qk_kernel,   cudaFuncAttributeMaxDynamicSharedMemorySize, smem_qk);
    cudaFuncSetAttribute(attn_kernel, cudaFuncAttributeMaxDynamicSharedMemorySize, smem_attn);
    cudaFuncSetAttribute(ov_kernel,   cudaFuncAttributeMaxDynamicSharedMemorySize, smem_ov);

    // 1) Q = (x @ Wq^T) / 8
    proj_kernel<<<dim3(8, 128), 256, smem_proj>>>(x, Wq, nullptr, nullptr, 0.125f, 0);
    // 2) QK = q_h @ Wk_h (per head, K=64)
    qk_kernel<<<dim3(8, 128, 8), 256, smem_qk>>>(Wk);
    // 3) attention per batch: scores, softmax, AL = attn @ l
    attn_kernel<<<1024, 256, smem_attn>>>(l);
    // 4) OV = AL_h @ Wv_h^T
    ov_kernel<<<dim3(128, 8), 256, smem_ov>>>(Wv);
    // 5) out = OV @ Wo^T + bo
    proj_kernel<<<dim3(8, 128), 256, smem_proj>>>(nullptr, Wo, out, bo, 1.0f, 1);
}

// round 4
// speedup vs baseline: 2.4182x; 1.7779x over previous
#include <cuda_runtime.h>
#include <cuda_fp16.h>
#include <cstdint>

// ---------------------------------------------------------------------------
// CrossAttentionDecoder, fp16 tensor-core pipeline (fp32 accumulate):
//   K1 proj  : g_Q  = half((x @ Wq^T) * 0.125)
//   K2 qk    : g_QK[b,h,i,:] = half(g_Q[b,i,h*64:+64] @ Wk[h*64:+64,:])
//   K3 attn  : per batch: scores = qk @ l^T (masked) -> softmax ->
//              g_AL = half(attn @ l)
//   K4 ov    : g_OV[:, h*64:+64] = half(g_AL_h @ Wv_h^T)
//   K5 proj  : out = g_OV @ Wo^T + bo   (fp32 out)
// fp16 mantissa == tf32 mantissa; fp32 accum => precision ~unchanged.
// ---------------------------------------------------------------------------

#define DIM 512
#define NLAT 128
#define NTOK 16
#define NHEAD 8
#define DH 64
#define NB 1024

// scratch (device globals: allocation-free), all half
__device__ __half g_Q [(size_t)NB * NTOK * DIM];          // 16.8 MB
__device__ __half g_QK[(size_t)NB * NHEAD * NTOK * DIM];  // 134 MB
__device__ __half g_AL[(size_t)NB * NHEAD * NTOK * DIM];  // 134 MB
__device__ __half g_OV[(size_t)NB * NTOK * DIM];          // 16.8 MB

// smem sizes in halves
#define PROJ_SMEM_H (128 * 72 + 64 * 72)
#define QK_SMEM_H   (128 * 72 + 64 * 72)
#define OV_SMEM_H   (128 * 72 + 64 * 72)
#define ATTN_SMEM_H (128 * 72 + 128 * 72 + 128 * 136)

__device__ __forceinline__ uint32_t packh2(float a, float b) {
    __half2 h = __floats2half2_rn(a, b);
    return *reinterpret_cast<uint32_t*>(&h);
}
__device__ __forceinline__ uint2 pack4(float4 v) {
    return make_uint2(packh2(v.x, v.y), packh2(v.z, v.w));
}
__device__ __forceinline__ void mma_fp16(float* c, uint32_t a0, uint32_t a1,
                                         uint32_t a2, uint32_t a3,
                                         uint32_t b0, uint32_t b1) {
    asm volatile(
        "mma.sync.aligned.m16n8k16.row.col.f32.f16.f16.f32 "
        "{%0,%1,%2,%3}, {%4,%5,%6,%7}, {%8,%9}, {%0,%1,%2,%3};\n"
        : "+f"(c[0]), "+f"(c[1]), "+f"(c[2]), "+f"(c[3])
        : "r"(a0), "r"(a1), "r"(a2), "r"(a3), "r"(b0), "r"(b1));
}
__device__ __forceinline__ uint32_t lds_u32(const __half* p) {
    return *reinterpret_cast<const uint32_t*>(p);
}

// ---------------------------------------------------------------------------
// K1/K5: C[M,512] = scale * A @ W^T (+bias). Block 128m x 64n.
// mode 0: A = x (fp32), C = g_Q (half).  mode 1: A = g_OV (half), C = out fp32.
// ---------------------------------------------------------------------------
__global__ __launch_bounds__(256) void proj_kernel(
    const float* __restrict__ A32, const float* __restrict__ W,
    float* __restrict__ Cout, const float* __restrict__ bias,
    float scale, int mode)
{
    extern __shared__ __half smh[];
    __half* As = smh;               // [128][72]
    __half* Ws = smh + 128 * 72;    // [64][72]  Ws[n][k]

    const int n0 = blockIdx.x * 64;
    const int m0 = blockIdx.y * 128;
    const int tid = threadIdx.x;
    const int warp = tid >> 5, lane = tid & 31;
    const int g = lane >> 2, t = lane & 3;
    const int mw = warp * 16;

    float c[8][4];
#pragma unroll
    for (int f = 0; f < 8; f++)
#pragma unroll
        for (int e = 0; e < 4; e++) c[f][e] = 0.f;

    for (int kc = 0; kc < 8; kc++) {
        const int k0g = kc * 64;
        if (mode == 0) {
#pragma unroll
            for (int it = 0; it < 8; it++) {        // A: 128 x 16 float4
                int idx = tid + it * 256;
                int r = idx >> 4, c4 = idx & 15;
                float4 v = *reinterpret_cast<const float4*>(
                    A32 + (size_t)(m0 + r) * DIM + k0g + c4 * 4);
                *reinterpret_cast<uint2*>(As + r * 72 + c4 * 4) = pack4(v);
            }
        } else {
#pragma unroll
            for (int it = 0; it < 4; it++) {        // A: 128 x 8 uint4 (halves)
                int idx = tid + it * 256;
                int r = idx >> 3, q = idx & 7;
                uint4 v = *reinterpret_cast<const uint4*>(
                    g_OV + (size_t)(m0 + r) * DIM + k0g + q * 8);
                *reinterpret_cast<uint4*>(As + r * 72 + q * 8) = v;
            }
        }
#pragma unroll
        for (int it = 0; it < 4; it++) {            // W: 64 x 16 float4
            int idx = tid + it * 256;
            int r = idx >> 4, c4 = idx & 15;
            float4 v = *reinterpret_cast<const float4*>(
                W + (size_t)(n0 + r) * DIM + k0g + c4 * 4);
            *reinterpret_cast<uint2*>(Ws + r * 72 + c4 * 4) = pack4(v);
        }
        __syncthreads();
#pragma unroll
        for (int ks = 0; ks < 4; ks++) {
            const int k0 = ks * 16;
            uint32_t a0 = lds_u32(As + (mw + g) * 72 + k0 + 2 * t);
            uint32_t a1 = lds_u32(As + (mw + g + 8) * 72 + k0 + 2 * t);
            uint32_t a2 = lds_u32(As + (mw + g) * 72 + k0 + 2 * t + 8);
            uint32_t a3 = lds_u32(As + (mw + g + 8) * 72 + k0 + 2 * t + 8);
#pragma unroll
            for (int f = 0; f < 8; f++) {
                uint32_t b0 = lds_u32(Ws + (f * 8 + g) * 72 + k0 + 2 * t);
                uint32_t b1 = lds_u32(Ws + (f * 8 + g) * 72 + k0 + 2 * t + 8);
                mma_fp16(c[f], a0, a1, a2, a3, b0, b1);
            }
        }
        __syncthreads();
    }
#pragma unroll
    for (int f = 0; f < 8; f++) {
        const int col = n0 + f * 8 + 2 * t;
        const int row0 = m0 + mw + g;
        if (mode == 0) {
            *reinterpret_cast<uint32_t*>(g_Q + (size_t)row0 * DIM + col) =
                packh2(c[f][0] * scale, c[f][1] * scale);
            *reinterpret_cast<uint32_t*>(g_Q + (size_t)(row0 + 8) * DIM + col) =
                packh2(c[f][2] * scale, c[f][3] * scale);
        } else {
            float b0 = bias[col], b1 = bias[col + 1];
            *reinterpret_cast<float2*>(Cout + (size_t)row0 * DIM + col) =
                make_float2(c[f][0] + b0, c[f][1] + b1);
            *reinterpret_cast<float2*>(Cout + (size_t)(row0 + 8) * DIM + col) =
                make_float2(c[f][2] + b0, c[f][3] + b1);
        }
    }
}

// ---------------------------------------------------------------------------
// K2: g_QK[b][h][i][e] = g_Q[b*16+i][h*64:+64] @ Wk[h*64:+64][e]   (K=64)
// grid (8 e-chunks, 128 mtiles, 8 heads)
// ---------------------------------------------------------------------------
__global__ __launch_bounds__(256) void qk_kernel(const float* __restrict__ Wk)
{
    extern __shared__ __half smh[];
    __half* As  = smh;              // [128][72]  As[r][k]
    __half* BsT = smh + 128 * 72;   // [64][72]   BsT[n][k] = Wk[h64+k][n0+n]

    const int n0 = blockIdx.x * 64;
    const int m0 = blockIdx.y * 128;
    const int h  = blockIdx.z;
    const int tid = threadIdx.x;
    const int warp = tid >> 5, lane = tid & 31;
    const int g = lane >> 2, t = lane & 3;
    const int mw = warp * 16;

    // stage A (half source): rows m0..+128, cols h*64..+64
#pragma unroll
    for (int it = 0; it < 4; it++) {
        int idx = tid + it * 256;
        int r = idx >> 3, q = idx & 7;
        uint4 v = *reinterpret_cast<const uint4*>(
            g_Q + (size_t)(m0 + r) * DIM + h * DH + q * 8);
        *reinterpret_cast<uint4*>(As + r * 72 + q * 8) = v;
    }
    // stage BsT transposed from fp32 Wk
#pragma unroll
    for (int it = 0; it < 4; it++) {
        int idx = tid + it * 256;
        int k = idx >> 4, q = idx & 15;          // k row of Wk, 4 n-values
        float4 v = *reinterpret_cast<const float4*>(
            Wk + (size_t)(h * DH + k) * DIM + n0 + q * 4);
        BsT[(q * 4 + 0) * 72 + k] = __float2half_rn(v.x);
        BsT[(q * 4 + 1) * 72 + k] = __float2half_rn(v.y);
        BsT[(q * 4 + 2) * 72 + k] = __float2half_rn(v.z);
        BsT[(q * 4 + 3) * 72 + k] = __float2half_rn(v.w);
    }
    __syncthreads();

    float c[8][4];
#pragma unroll
    for (int f = 0; f < 8; f++)
#pragma unroll
        for (int e = 0; e < 4; e++) c[f][e] = 0.f;

#pragma unroll
    for (int ks = 0; ks < 4; ks++) {
        const int k0 = ks * 16;
        uint32_t a0 = lds_u32(As + (mw + g) * 72 + k0 + 2 * t);
        uint32_t a1 = lds_u32(As + (mw + g + 8) * 72 + k0 + 2 * t);
        uint32_t a2 = lds_u32(As + (mw + g) * 72 + k0 + 2 * t + 8);
        uint32_t a3 = lds_u32(As + (mw + g + 8) * 72 + k0 + 2 * t + 8);
#pragma unroll
        for (int f = 0; f < 8; f++) {
            uint32_t b0 = lds_u32(BsT + (f * 8 + g) * 72 + k0 + 2 * t);
            uint32_t b1 = lds_u32(BsT + (f * 8 + g) * 72 + k0 + 2 * t + 8);
            mma_fp16(c[f], a0, a1, a2, a3, b0, b1);
        }
    }

    const int bb = (m0 + mw) >> 4;   // batch index (warp-uniform)
#pragma unroll
    for (int f = 0; f < 8; f++) {
        const int col = n0 + f * 8 + 2 * t;
        size_t o0 = (((size_t)bb * NHEAD + h) * NTOK + g) * DIM + col;
        size_t o1 = (((size_t)bb * NHEAD + h) * NTOK + g + 8) * DIM + col;
        *reinterpret_cast<uint32_t*>(g_QK + o0) = packh2(c[f][0], c[f][1]);
        *reinterpret_cast<uint32_t*>(g_QK + o1) = packh2(c[f][2], c[f][3]);
    }
}

// ---------------------------------------------------------------------------
// K3: per-batch attention. warp = head.
// ---------------------------------------------------------------------------
__global__ __launch_bounds__(256) void attn_kernel(const float* __restrict__ l)
{
    extern __shared__ __half smh[];
    __half* l_s  = smh;                    // phase A: [128][72]; phase B: l_t [64][136]
    __half* qk_s = smh + 128 * 72;         // [128][72]
    __half* s_s  = qk_s + 128 * 72;        // [128][136] attn weights

    const int b = blockIdx.x;
    const int m = b & (NLAT - 1);
    const int njt = (m >> 5) + 1;          // 32-row j tiles needed
    const int rows = njt << 5;

    const int tid = threadIdx.x;
    const int h = tid >> 5, lane = tid & 31;
    const int g = lane >> 2, t = lane & 3;

    const float*  lb  = l + (size_t)b * NLAT * DIM;
    const __half* qkb = g_QK + (size_t)b * NHEAD * NTOK * DIM;

    float cs[16][4];
#pragma unroll
    for (int f = 0; f < 16; f++)
#pragma unroll
        for (int e = 0; e < 4; e++) cs[f][e] = 0.f;

    // ---- phase A: scores = qk @ l^T ----
    for (int ec = 0; ec < 8; ec++) {
        const int e0 = ec * 64;
#pragma unroll
        for (int it = 0; it < 4; it++) {           // qk_s: 128 x 8 uint4
            int idx = tid + it * 256;
            int r = idx >> 3, q = idx & 7;
            uint4 v = *reinterpret_cast<const uint4*>(
                qkb + (size_t)r * DIM + e0 + q * 8);
            *reinterpret_cast<uint4*>(qk_s + r * 72 + q * 8) = v;
        }
#pragma unroll
        for (int it = 0; it < 8; it++) {           // l_s rows [0,rows)
            int idx = tid + it * 256;
            int r = idx >> 4, c4 = idx & 15;
            if (r < rows) {
                float4 v = *reinterpret_cast<const float4*>(
                    lb + (size_t)r * DIM + e0 + c4 * 4);
                *reinterpret_cast<uint2*>(l_s + r * 72 + c4 * 4) = pack4(v);
            }
        }
        __syncthreads();
#pragma unroll
        for (int ks = 0; ks < 4; ks++) {
            const int k0 = ks * 16;
            uint32_t a0 = lds_u32(qk_s + (h * 16 + g) * 72 + k0 + 2 * t);
            uint32_t a1 = lds_u32(qk_s + (h * 16 + g + 8) * 72 + k0 + 2 * t);
            uint32_t a2 = lds_u32(qk_s + (h * 16 + g) * 72 + k0 + 2 * t + 8);
            uint32_t a3 = lds_u32(qk_s + (h * 16 + g + 8) * 72 + k0 + 2 * t + 8);
#pragma unroll
            for (int jt = 0; jt < 4; jt++) {
                if (jt < njt) {
#pragma unroll
                    for (int jn = 0; jn < 4; jn++) {
                        const int jr = jt * 32 + jn * 8;
                        uint32_t b0 = lds_u32(l_s + (jr + g) * 72 + k0 + 2 * t);
                        uint32_t b1 = lds_u32(l_s + (jr + g) * 72 + k0 + 2 * t + 8);
                        mma_fp16(cs[jt * 4 + jn], a0, a1, a2, a3, b0, b1);
                    }
                }
            }
        }
        __syncthreads();
    }

    // ---- masked softmax (rows g and g+8 per thread) ----
    float mx0 = -1e30f, mx1 = -1e30f;
#pragma unroll
    for (int f = 0; f < 16; f++) {
        const int jb = f * 8 + 2 * t;
#pragma unroll
        for (int e = 0; e < 2; e++) {
            if (jb + e > m) { cs[f][e] = -1e30f; cs[f][2 + e] = -1e30f; }
            mx0 = fmaxf(mx0, cs[f][e]);
            mx1 = fmaxf(mx1, cs[f][2 + e]);
        }
    }
    mx0 = fmaxf(mx0, __shfl_xor_sync(0xffffffffu, mx0, 1));
    mx0 = fmaxf(mx0, __shfl_xor_sync(0xffffffffu, mx0, 2));
    mx1 = fmaxf(mx1, __shfl_xor_sync(0xffffffffu, mx1, 1));
    mx1 = fmaxf(mx1, __shfl_xor_sync(0xffffffffu, mx1, 2));
    float s0 = 0.f, s1 = 0.f;
#pragma unroll
    for (int f = 0; f < 16; f++)
#pragma unroll
        for (int e = 0; e < 2; e++) {
            cs[f][e] = __expf(cs[f][e] - mx0);         s0 += cs[f][e];
            cs[f][2 + e] = __expf(cs[f][2 + e] - mx1); s1 += cs[f][2 + e];
        }
    s0 += __shfl_xor_sync(0xffffffffu, s0, 1);
    s0 += __shfl_xor_sync(0xffffffffu, s0, 2);
    s1 += __shfl_xor_sync(0xffffffffu, s1, 1);
    s1 += __shfl_xor_sync(0xffffffffu, s1, 2);
    const float i0 = 1.f / s0, i1 = 1.f / s1;
#pragma unroll
    for (int f = 0; f < 16; f++) {
        const int jb = f * 8 + 2 * t;
        *reinterpret_cast<uint32_t*>(s_s + (h * 16 + g) * 136 + jb) =
            packh2(cs[f][0] * i0, cs[f][1] * i0);
        *reinterpret_cast<uint32_t*>(s_s + (h * 16 + g + 8) * 136 + jb) =
            packh2(cs[f][2] * i1, cs[f][3] * i1);
    }
    // s_s rows are warp-private (written and read by the same warp).

    // ---- phase B: AL = attn @ l ----
    __half* l_t = l_s;                     // [64][136]  l_t[e][j] = l[j][e0+e]
    for (int ec = 0; ec < 8; ec++) {
        const int e0 = ec * 64;
        __syncthreads();                   // l_s/l_t reuse across iterations
#pragma unroll
        for (int it = 0; it < 8; it++) {
            int idx = tid + it * 256;
            int j = idx >> 4, c4 = idx & 15;
            if (j < rows) {
                float4 v = *reinterpret_cast<const float4*>(
                    lb + (size_t)j * DIM + e0 + c4 * 4);
                l_t[(c4 * 4 + 0) * 136 + j] = __float2half_rn(v.x);
                l_t[(c4 * 4 + 1) * 136 + j] = __float2half_rn(v.y);
                l_t[(c4 * 4 + 2) * 136 + j] = __float2half_rn(v.z);
                l_t[(c4 * 4 + 3) * 136 + j] = __float2half_rn(v.w);
            }
        }
        __syncthreads();

        float co[8][4];
#pragma unroll
        for (int en = 0; en < 8; en++)
#pragma unroll
            for (int e = 0; e < 4; e++) co[en][e] = 0.f;

        for (int jk = 0; jk < njt * 2; jk++) {     // K = j, 16 per step
            const int k0 = jk * 16;
            uint32_t a0 = lds_u32(s_s + (h * 16 + g) * 136 + k0 + 2 * t);
            uint32_t a1 = lds_u32(s_s + (h * 16 + g + 8) * 136 + k0 + 2 * t);
            uint32_t a2 = lds_u32(s_s + (h * 16 + g) * 136 + k0 + 2 * t + 8);
            uint32_t a3 = lds_u32(s_s + (h * 16 + g + 8) * 136 + k0 + 2 * t + 8);
#pragma unroll
            for (int en = 0; en < 8; en++) {
                uint32_t b0 = lds_u32(l_t + (en * 8 + g) * 136 + k0 + 2 * t);
                uint32_t b1 = lds_u32(l_t + (en * 8 + g) * 136 + k0 + 2 * t + 8);
                mma_fp16(co[en], a0, a1, a2, a3, b0, b1);
            }
        }
#pragma unroll
        for (int en = 0; en < 8; en++) {
            const int col = e0 + en * 8 + 2 * t;
            size_t o0 = ((size_t)b * (NHEAD * NTOK) + h * 16 + g) * DIM + col;
            size_t o1 = ((size_t)b * (NHEAD * NTOK) + h * 16 + g + 8) * DIM + col;
            *reinterpret_cast<uint32_t*>(g_AL + o0) = packh2(co[en][0], co[en][1]);
            *reinterpret_cast<uint32_t*>(g_AL + o1) = packh2(co[en][2], co[en][3]);
        }
    }
}

// ---------------------------------------------------------------------------
// K4: g_OV[b*16+i][h*64+d] = g_AL[b][h][i][:] @ Wv[h*64+d][:]  (K=512, N=64)
// grid (128 btiles of 8 batches, 8 heads)
// ---------------------------------------------------------------------------
__global__ __launch_bounds__(256) void ov_kernel(const float* __restrict__ Wv)
{
    extern __shared__ __half smh[];
    __half* As = smh;               // [128][72]
    __half* Ws = smh + 128 * 72;    // [64][72]  Ws[d][k] (k = e)

    const int bt = blockIdx.x;
    const int h  = blockIdx.y;
    const int tid = threadIdx.x;
    const int warp = tid >> 5, lane = tid & 31;
    const int g = lane >> 2, t = lane & 3;
    const int mw = warp * 16;

    float c[8][4];
#pragma unroll
    for (int f = 0; f < 8; f++)
#pragma unroll
        for (int e = 0; e < 4; e++) c[f][e] = 0.f;

    for (int kc = 0; kc < 8; kc++) {
        const int k0g = kc * 64;
#pragma unroll
        for (int it = 0; it < 4; it++) {           // A: 128 AL-rows x 8 uint4
            int idx = tid + it * 256;
            int r = idx >> 3, q = idx & 7;
            size_t gr = (((size_t)(bt * 8 + (r >> 4)) * NHEAD + h) * NTOK + (r & 15));
            uint4 v = *reinterpret_cast<const uint4*>(
                g_AL + gr * DIM + k0g + q * 8);
            *reinterpret_cast<uint4*>(As + r * 72 + q * 8) = v;
        }
#pragma unroll
        for (int it = 0; it < 4; it++) {           // Wv_h: 64 x 16 float4
            int idx = tid + it * 256;
            int d = idx >> 4, c4 = idx & 15;
            float4 v = *reinterpret_cast<const float4*>(
                Wv + (size_t)(h * DH + d) * DIM + k0g + c4 * 4);
            *reinterpret_cast<uint2*>(Ws + d * 72 + c4 * 4) = pack4(v);
        }
        __syncthreads();
#pragma unroll
        for (int ks = 0; ks < 4; ks++) {
            const int k0 = ks * 16;
            uint32_t a0 = lds_u32(As + (mw + g) * 72 + k0 + 2 * t);
            uint32_t a1 = lds_u32(As + (mw + g + 8) * 72 + k0 + 2 * t);
            uint32_t a2 = lds_u32(As + (mw + g) * 72 + k0 + 2 * t + 8);
            uint32_t a3 = lds_u32(As + (mw + g + 8) * 72 + k0 + 2 * t + 8);
#pragma unroll
            for (int f = 0; f < 8; f++) {
                uint32_t b0 = lds_u32(Ws + (f * 8 + g) * 72 + k0 + 2 * t);
                uint32_t b1 = lds_u32(Ws + (f * 8 + g) * 72 + k0 + 2 * t + 8);
                mma_fp16(c[f], a0, a1, a2, a3, b0, b1);
            }
        }
        __syncthreads();
    }

    const int bb = bt * 8 + warp;
#pragma unroll
    for (int f = 0; f < 8; f++) {
        const int col = h * DH + f * 8 + 2 * t;
        size_t o0 = ((size_t)bb * NTOK + g) * DIM + col;
        size_t o1 = ((size_t)bb * NTOK + g + 8) * DIM + col;
        *reinterpret_cast<uint32_t*>(g_OV + o0) = packh2(c[f][0], c[f][1]);
        *reinterpret_cast<uint32_t*>(g_OV + o1) = packh2(c[f][2], c[f][3]);
    }
}

// ---------------------------------------------------------------------------
extern "C" void kernel_launch(void* const* d_in, const int* in_sizes, int n_in,
                              void* d_out, int out_size)
{
    const float* x  = (const float*)d_in[0];
    const float* l  = (const float*)d_in[1];
    const float* Wq = (const float*)d_in[2];
    const float* Wk = (const float*)d_in[3];
    const float* Wv = (const float*)d_in[4];
    const float* Wo = (const float*)d_in[5];
    const float* bo = (const float*)d_in[6];
    float* out = (float*)d_out;

    const int smem_proj = PROJ_SMEM_H * 2;
    const int smem_qk   = QK_SMEM_H * 2;
    const int smem_attn = ATTN_SMEM_H * 2;
    const int smem_ov   = OV_SMEM_H * 2;

    cudaFuncSetAttribute(proj_kernel, cudaFuncAttributeMaxDynamicSharedMemorySize, smem_proj);
    cudaFuncSetAttribute(qk_kernel,   cudaFuncAttributeMaxDynamicSharedMemorySize, smem_qk);
    cudaFuncSetAttribute(attn_kernel, cudaFuncAttributeMaxDynamicSharedMemorySize, smem_attn);
    cudaFuncSetAttribute(ov_kernel,   cudaFuncAttributeMaxDynamicSharedMemorySize, smem_ov);

    // 1) Q = (x @ Wq^T) / 8  -> half
    proj_kernel<<<dim3(8, 128), 256, smem_proj>>>(x, Wq, nullptr, nullptr, 0.125f, 0);
    // 2) QK = q_h @ Wk_h (per head, K=64)
    qk_kernel<<<dim3(8, 128, 8), 256, smem_qk>>>(Wk);
    // 3) attention per batch: scores, softmax, AL = attn @ l
    attn_kernel<<<1024, 256, smem_attn>>>(l);
    // 4) OV = AL_h @ Wv_h^T
    ov_kernel<<<dim3(128, 8), 256, smem_ov>>>(Wv);
    // 5) out = OV @ Wo^T + bo  (fp32)
    proj_kernel<<<dim3(8, 128), 256, smem_proj>>>(nullptr, Wo, out, bo, 1.0f, 1);
}